// round 7
// baseline (speedup 1.0000x reference)
#include <cuda_runtime.h>
#include <cstdint>

// ---------------------------------------------------------------------------
// QCNN 13 qubits, B=2 -> 23 two-qubit gates. Grid 16 x 512, cluster size 8
// (one 8-CTA cluster per batch; 1024 amps per CTA, 2 per thread in regs).
// All 23 gates are warp-shuffle gates; 2 smem remaps + 1 DSMEM exchange.
// ---------------------------------------------------------------------------

#define NT      512
#define NBLK    16
#define CLUSTER 8

typedef unsigned long long u64;

#define FMA2(d,a,b,c) asm("fma.rn.f32x2 %0,%1,%2,%3;" : "=l"(d) : "l"(a), "l"(b), "l"(c))
#define MUL2(d,a,b)   asm("mul.rn.f32x2 %0,%1,%2;"    : "=l"(d) : "l"(a), "l"(b))

__device__ __forceinline__ u64 swap64(u64 a) {
    unsigned lo, hi;
    asm("mov.b64 {%0,%1}, %2;" : "=r"(lo), "=r"(hi) : "l"(a));
    u64 r;
    asm("mov.b64 %0, {%1,%2};" : "=l"(r) : "r"(hi), "r"(lo));
    return r;
}
__device__ __forceinline__ u64 pack2(float x, float y) {
    u64 r; asm("mov.b64 %0, {%1,%2};" : "=l"(r) : "f"(x), "f"(y)); return r;
}
__device__ __forceinline__ void unpack2(u64 v, float& x, float& y) {
    asm("mov.b64 {%0,%1}, %2;" : "=f"(x), "=f"(y) : "l"(v));
}
__device__ __forceinline__ float sq64(u64 v) {
    float x, y; unpack2(v, x, y);
    return fmaf(x, x, y * y);
}
__device__ __forceinline__ u64 shx64(u64 v, int m) {
    return __shfl_xor_sync(0xffffffffu, v, m);
}

// Remap-1 swizzle: fold bits 4..8 of the 10-bit index into bits 0..3.
// Verified conflict-free for alpha-store and beta-load half-warp windows.
__device__ __forceinline__ unsigned swzA(unsigned l) {
    unsigned h = (l >> 4) & 31u;
    return l ^ ((h & 15u) ^ ((h & 16u) ? 6u : 0u));
}
// Remap-2 swizzle: fold bits 5..8 into bits 0..3.
// Verified conflict-free for gamma-store and delta-load half-warp windows.
__device__ __forceinline__ unsigned swzB(unsigned m) {
    return m ^ ((m >> 5) & 15u);
}

// Both gate bits in lane bits LP (high), LQ (low). V[r][x] = U[r][r^x],
// rows padded to 5 ulonglong2 (80B) -> conflict-free LDS.128.
template <int LP, int LQ, int L>
__device__ __forceinline__ void bothlane(u64& v0, u64& v1, unsigned lane,
                                         const ulonglong2* __restrict__ Vt) {
    unsigned r = (((lane >> LP) & 1u) << 1) | ((lane >> LQ) & 1u);
    const ulonglong2* row = Vt + L * 20 + (int)r * 5;
    ulonglong2 e0 = row[0], e1 = row[1], e2 = row[2], e3 = row[3];
    u64 b0 = shx64(v0, 1 << LQ), b1 = shx64(v1, 1 << LQ);
    u64 c0 = shx64(v0, 1 << LP), c1 = shx64(v1, 1 << LP);
    u64 d0 = shx64(v0, (1 << LP) | (1 << LQ)), d1 = shx64(v1, (1 << LP) | (1 << LQ));
    u64 t, s;
    MUL2(t, e0.x, v0); FMA2(t, e0.y, swap64(v0), t);
    FMA2(t, e1.x, b0, t); FMA2(t, e1.y, swap64(b0), t);
    FMA2(t, e2.x, c0, t); FMA2(t, e2.y, swap64(c0), t);
    FMA2(t, e3.x, d0, t); FMA2(t, e3.y, swap64(d0), t);
    MUL2(s, e0.x, v1); FMA2(s, e0.y, swap64(v1), s);
    FMA2(s, e1.x, b1, s); FMA2(s, e1.y, swap64(b1), s);
    FMA2(s, e2.x, c1, s); FMA2(s, e2.y, swap64(c1), s);
    FMA2(s, e3.x, d1, s); FMA2(s, e3.y, swap64(d1), s);
    v0 = t; v1 = s;
}

// High gate bit in lane bit LH, low gate bit = element bit (v0 <-> v1).
template <int LH, int L>
__device__ __forceinline__ void elemlane(u64& v0, u64& v1, unsigned lane,
                                         const ulonglong2* __restrict__ Vt) {
    unsigned bh = (lane >> LH) & 1u;
    const ulonglong2* r0p = Vt + L * 20 + (int)(bh << 1) * 5;
    const ulonglong2* r1p = r0p + 5;
    ulonglong2 a0 = r0p[0], a1 = r0p[1], a2 = r0p[2], a3 = r0p[3];
    ulonglong2 g0 = r1p[0], g1 = r1p[1], g2 = r1p[2], g3 = r1p[3];
    u64 w0 = shx64(v0, 1 << LH), w1 = shx64(v1, 1 << LH);
    u64 t, s;
    MUL2(t, a0.x, v0); FMA2(t, a0.y, swap64(v0), t);
    FMA2(t, a1.x, v1, t); FMA2(t, a1.y, swap64(v1), t);
    FMA2(t, a2.x, w0, t); FMA2(t, a2.y, swap64(w0), t);
    FMA2(t, a3.x, w1, t); FMA2(t, a3.y, swap64(w1), t);
    MUL2(s, g0.x, v1); FMA2(s, g0.y, swap64(v1), s);
    FMA2(s, g1.x, v0, s); FMA2(s, g1.y, swap64(v0), s);
    FMA2(s, g2.x, w1, s); FMA2(s, g2.y, swap64(w1), s);
    FMA2(s, g3.x, w0, s); FMA2(s, g3.y, swap64(w0), s);
    v0 = t; v1 = s;
}

__device__ __forceinline__ unsigned sm32(const void* p) {
    return (unsigned)__cvta_generic_to_shared(p);
}
__device__ __forceinline__ unsigned mapa32(unsigned addr, unsigned rank) {
    unsigned ra;
    asm("mapa.shared::cluster.u32 %0, %1, %2;" : "=r"(ra) : "r"(addr), "r"(rank));
    return ra;
}
__device__ __forceinline__ u64 dsld64r(unsigned ra) {
    u64 v;
    asm volatile("ld.shared::cluster.b64 %0, [%1];" : "=l"(v) : "r"(ra));
    return v;
}
__device__ __forceinline__ void dsst64r(unsigned ra, u64 v) {
    asm volatile("st.shared::cluster.b64 [%0], %1;" :: "r"(ra), "l"(v) : "memory");
}
#define CLUSTER_SYNC() do { \
    asm volatile("barrier.cluster.arrive.aligned;" ::: "memory"); \
    asm volatile("barrier.cluster.wait.aligned;"   ::: "memory"); \
} while (0)

__global__ void __launch_bounds__(NT, 1)
qcnn_kernel(const float* __restrict__ pr, const float* __restrict__ pi,
            const float* __restrict__ Hr, const float* __restrict__ Hi,
            float* __restrict__ out)
{
    __shared__ u64 bufR[1024];         // remap scratch (CTA-private)
    __shared__ u64 bufS[1024];         // cluster exchange buffer
    __shared__ ulonglong2 Vt[80];      // V[L][r][x] = U[r][r^x], rows padded to 5
    __shared__ float2 red2[16];
    __shared__ u64 spartArr[CLUSTER];  // rank 0 only: pushed (n,s) partials

    const unsigned t    = threadIdx.x;
    const unsigned lane = t & 31u;
    const unsigned wq   = t >> 5;      // 4 warp bits (16 warps)
    const unsigned b    = blockIdx.x >> 3;
    unsigned rank;
    asm("mov.u32 %0, %%cluster_ctarank;" : "=r"(rank));   // 3 bits

    // ---- Alpha position map: p0..2=w0..2, p3=e, p4..8=lane0..4, p9=w3;
    //      chunk bits (rank) = positions 10..12. Each thread: 2 amps. ----
    const float* prb = pr + (b << 13);
    const float* pib = pi + (b << 13);
    unsigned gi0 = (wq & 7u) | (lane << 4) | ((wq >> 3) << 9) | (rank << 10);
    u64 v0 = pack2(prb[gi0], pib[gi0]);
    u64 v1 = pack2(prb[gi0 | 8u], pib[gi0 | 8u]);
    float ns = sq64(v0) + sq64(v1);

    // ---- warps 0..3: expm(H - H^dag), one layer per warp (halves duplicate);
    //      writes XOR-permuted V table (identical to round-6 passing code) ----
    if (t < 128u) {
        const int L = (int)wq;
        const int e = (int)(lane & 15u);
        const int i = e >> 2, j = e & 3;
        const unsigned seg = lane & 16u;
        const float* HrL = Hr + L * 16;
        const float* HiL = Hi + L * 16;
        float ar = HrL[e] - HrL[j * 4 + i];
        float ai = HiL[e] + HiL[j * 4 + i];
        float f2 = fmaf(ar, ar, ai * ai);
#pragma unroll
        for (int o = 8; o; o >>= 1) f2 += __shfl_xor_sync(0xffffffffu, f2, o);
        float fro = sqrtf(f2);
        int s = 0; float x = fro;
        while (x > 0.25f && s < 14) { x *= 0.5f; ++s; }
        float sc = ldexpf(1.f, -s);
        float Ar = ar * sc, Ai = ai * sc;
        float Tr = Ar, Ti = Ai;
        float Er = Ar + ((i == j) ? 1.f : 0.f), Ei = Ai;
#pragma unroll 1
        for (int k = 2; k <= 9; ++k) {
            float accr = 0.f, acci = 0.f;
#pragma unroll
            for (int m = 0; m < 4; ++m) {
                unsigned sT = seg | (unsigned)(i * 4 + m);
                unsigned sA = seg | (unsigned)(m * 4 + j);
                float tr = __shfl_sync(0xffffffffu, Tr, sT);
                float ti = __shfl_sync(0xffffffffu, Ti, sT);
                float br = __shfl_sync(0xffffffffu, Ar, sA);
                float bi = __shfl_sync(0xffffffffu, Ai, sA);
                accr = fmaf(tr, br, fmaf(-ti, bi, accr));
                acci = fmaf(tr, bi, fmaf( ti, br, acci));
            }
            float inv = 1.f / (float)k;
            Tr = accr * inv; Ti = acci * inv;
            Er += Tr; Ei += Ti;
        }
#pragma unroll 1
        for (int q = 0; q < s; ++q) {
            float accr = 0.f, acci = 0.f;
#pragma unroll
            for (int m = 0; m < 4; ++m) {
                unsigned sR = seg | (unsigned)(i * 4 + m);
                unsigned sC = seg | (unsigned)(m * 4 + j);
                float rr = __shfl_sync(0xffffffffu, Er, sR);
                float ri = __shfl_sync(0xffffffffu, Ei, sR);
                float cr = __shfl_sync(0xffffffffu, Er, sC);
                float ci = __shfl_sync(0xffffffffu, Ei, sC);
                accr = fmaf(rr, cr, fmaf(-ri, ci, accr));
                acci = fmaf(rr, ci, fmaf( ri, cr, acci));
            }
            Er = accr; Ei = acci;
        }
        if (lane < 16u)
            Vt[L * 20 + i * 5 + (i ^ j)] = make_ulonglong2(pack2(Er, Er), pack2(-Ei, Ei));
    }
    __syncthreads();

    // ---- Pass alpha ----
    bothlane<4,3,0>(v0, v1, lane, Vt);     // L0 (8,7)
    bothlane<2,1,0>(v0, v1, lane, Vt);     // L0 (6,5)
    elemlane<0,0>  (v0, v1, lane, Vt);     // L0 (4,3)
    bothlane<3,2,0>(v0, v1, lane, Vt);     // L0 (7,6)
    bothlane<1,0,0>(v0, v1, lane, Vt);     // L0 (5,4)
    bothlane<3,1,1>(v0, v1, lane, Vt);     // L1 (7,5)

    // ---- Remap alpha -> beta (p0..3=lane0..3, p4=e, p5=lane4, p6..8=w0..2, p9=w3)
    {
        unsigned la0 = (wq & 7u) | (lane << 4) | ((wq >> 3) << 9);
        bufR[swzA(la0)]      = v0;
        bufR[swzA(la0 | 8u)] = v1;
        __syncthreads();
        unsigned lb0 = (lane & 15u) | ((lane >> 4) << 5) | ((wq & 7u) << 6) | ((wq >> 3) << 9);
        v0 = bufR[swzA(lb0)];
        v1 = bufR[swzA(lb0 | 16u)];
    }

    // ---- Pass beta ----
    bothlane<2,1,0>(v0, v1, lane, Vt);     // L0 (2,1)
    bothlane<3,2,0>(v0, v1, lane, Vt);     // L0 (3,2)
    bothlane<1,0,0>(v0, v1, lane, Vt);     // L0 (1,0)
    bothlane<3,1,1>(v0, v1, lane, Vt);     // L1 (3,1)
    bothlane<4,3,1>(v0, v1, lane, Vt);     // L1 (5,3)
    bothlane<1,0,1>(v0, v1, lane, Vt);     // L1 (1,0)

    // ---- Cluster exchange. bufS layout = identity on positions 0..9 (beta
    //      map IS the identity: l bit k == position k). Gamma thread needs:
    //      p0,p1=wq0,wq1; p5,p6=wq2,wq3; p7=e; p8..12=lane0..4; p2..4=rank.
    //      -> owner = lane2..4, owner-local l = wq0,wq1 | rank<<2 | wq2,wq3<<5
    //         | e<<7 | lane0,lane1<<8.
    {
        unsigned lb0 = (lane & 15u) | ((lane >> 4) << 5) | ((wq & 7u) << 6) | ((wq >> 3) << 9);
        bufS[lb0]       = v0;   // e = 0 at bit 4
        bufS[lb0 | 16u] = v1;   // e = 1
        CLUSTER_SYNC();
        const unsigned base = sm32(bufS);
        unsigned owner = (lane >> 2) & 7u;
        unsigned lac = (wq & 3u) | (rank << 2) | (((wq >> 2) & 3u) << 5) | ((lane & 3u) << 8);
        unsigned ra = mapa32(base + lac * 8u, owner);   // one mapa, two loads
        v0 = dsld64r(ra);            // e=0 (position 7 = 0)
        v1 = dsld64r(ra + 1024u);    // e=1 (+128 slots * 8B)
    }

    // ---- Pass gamma (p8..12 = lane0..4, p7 = elem, p0,p1,p5,p6 = warp) ----
    bothlane<4,3,0>(v0, v1, lane, Vt);     // L0 (12,11)
    bothlane<2,1,0>(v0, v1, lane, Vt);     // L0 (10,9)
    bothlane<3,2,0>(v0, v1, lane, Vt);     // L0 (11,10)
    bothlane<1,0,0>(v0, v1, lane, Vt);     // L0 (9,8)
    bothlane<3,1,1>(v0, v1, lane, Vt);     // L1 (11,9)
    elemlane<1,1>  (v0, v1, lane, Vt);     // L1 (9,7): high=pos9(lane1), low=pos7(elem)

    // ---- Remap gamma -> delta. Canonical m-bits = positions [0,1,5,6,7,8,9,10,11,12].
    //      gamma: m0..3=wq, m4=e, m5..9=lane. delta: m0..3=lane0..3, m4=e,
    //      m5=wq0, m6=lane4, m7..9=wq1..3. ----
    {
        unsigned mg0 = (wq & 15u) | (lane << 5);
        bufR[swzB(mg0)]       = v0;
        bufR[swzB(mg0 | 16u)] = v1;
        __syncthreads();
        unsigned md0 = (lane & 15u) | ((wq & 1u) << 5) | ((lane >> 4) << 6) | ((wq >> 1) << 7);
        v0 = bufR[swzB(md0)];
        v1 = bufR[swzB(md0 | 16u)];
    }

    // ---- Pass delta (p0=lane0, p1=lane1, p5=lane2, p6=lane3, p9=lane4, p7=e) ----
    bothlane<4,2,2>(v0, v1, lane, Vt);     // L2 (9,5)
    bothlane<1,0,2>(v0, v1, lane, Vt);     // L2 (1,0)
    bothlane<2,1,2>(v0, v1, lane, Vt);     // L2 (5,1)
    bothlane<0,4,2>(v0, v1, lane, Vt);     // L2 (0,9): high=pos0(lane0), low=pos9(lane4)
    bothlane<2,0,3>(v0, v1, lane, Vt);     // L3 (5,0)

    // ---- Readout: P(position 0 == 0); position 0 = lane bit 0 ----
    float ls = (lane & 1u) ? 0.f : (sq64(v0) + sq64(v1));
#pragma unroll
    for (int o = 16; o; o >>= 1) {
        ns += __shfl_xor_sync(0xffffffffu, ns, o);
        ls += __shfl_xor_sync(0xffffffffu, ls, o);
    }
    if (lane == 0u) red2[wq] = make_float2(ns, ls);
    __syncthreads();

    // ---- Push CTA partial (n,s) to rank 0's smem; ordered by cluster barrier
    if (t == 0u) {
        float n = 0.f, s = 0.f;
#pragma unroll
        for (int w = 0; w < 16; ++w) { n += red2[w].x; s += red2[w].y; }
        unsigned ra = mapa32(sm32(&spartArr[rank]), 0u);
        dsst64r(ra, pack2(n, s));
    }

    // Final sync: orders pushes before rank 0's local reads AND guarantees all
    // DSMEM reads of peers' bufS finished before any CTA exits.
    CLUSTER_SYNC();
    if (rank == 0u && t == 0u) {
        float n = 0.f, s = 0.f;
#pragma unroll
        for (unsigned r = 0; r < CLUSTER; ++r) {
            float x, y; unpack2(spartArr[r], x, y);
            n += x; s += y;
        }
        out[b] = s / n;
    }
}

extern "C" void kernel_launch(void* const* d_in, const int* in_sizes, int n_in,
                              void* d_out, int out_size) {
    (void)in_sizes; (void)n_in; (void)out_size;
    const float* pr = (const float*)d_in[0];
    const float* pi = (const float*)d_in[1];
    const float* Hr = (const float*)d_in[2];
    const float* Hi = (const float*)d_in[3];
    float* out = (float*)d_out;

    cudaLaunchConfig_t cfg = {};
    cfg.gridDim  = dim3(NBLK, 1, 1);
    cfg.blockDim = dim3(NT, 1, 1);
    cfg.dynamicSmemBytes = 0;
    cfg.stream = 0;
    cudaLaunchAttribute attr[1];
    attr[0].id = cudaLaunchAttributeClusterDimension;
    attr[0].val.clusterDim.x = CLUSTER;
    attr[0].val.clusterDim.y = 1;
    attr[0].val.clusterDim.z = 1;
    cfg.attrs = attr;
    cfg.numAttrs = 1;

    cudaLaunchKernelEx(&cfg, qcnn_kernel, pr, pi, Hr, Hi, out);
}

// round 8
// speedup vs baseline: 1.1335x; 1.1335x over previous
#include <cuda_runtime.h>
#include <cstdint>

// ---------------------------------------------------------------------------
// QCNN 13 qubits, B=2 -> 23 two-qubit gates. Grid 32 x 256, one 16-CTA
// cluster per batch. Amplitudes in registers (2/thread); all 23 gates are
// warp-shuffle gates. 2 smem remaps + 1 DSMEM cluster exchange.
// R8: tree-structured packed FMA (depth 16 instead of 32) in gates and expm.
// ---------------------------------------------------------------------------

#define NT      256
#define NBLK    32
#define CLUSTER 16

typedef unsigned long long u64;

#define FMA2(d,a,b,c) asm("fma.rn.f32x2 %0,%1,%2,%3;" : "=l"(d) : "l"(a), "l"(b), "l"(c))
#define MUL2(d,a,b)   asm("mul.rn.f32x2 %0,%1,%2;"    : "=l"(d) : "l"(a), "l"(b))
#define ADD2(d,a,b)   asm("add.rn.f32x2 %0,%1,%2;"    : "=l"(d) : "l"(a), "l"(b))

__device__ __forceinline__ u64 swap64(u64 a) {
    unsigned lo, hi;
    asm("mov.b64 {%0,%1}, %2;" : "=r"(lo), "=r"(hi) : "l"(a));
    u64 r;
    asm("mov.b64 %0, {%1,%2};" : "=l"(r) : "r"(hi), "r"(lo));
    return r;
}
__device__ __forceinline__ u64 pack2(float x, float y) {
    u64 r; asm("mov.b64 %0, {%1,%2};" : "=l"(r) : "f"(x), "f"(y)); return r;
}
__device__ __forceinline__ void unpack2(u64 v, float& x, float& y) {
    asm("mov.b64 {%0,%1}, %2;" : "=f"(x), "=f"(y) : "l"(v));
}
__device__ __forceinline__ float sq64(u64 v) {
    float x, y; unpack2(v, x, y);
    return fmaf(x, x, y * y);
}
__device__ __forceinline__ u64 shx64(u64 v, int m) {
    return __shfl_xor_sync(0xffffffffu, v, m);
}

// Remap fold: bits 4..8 of the 9-bit local index folded into bits 0..3.
__device__ __forceinline__ unsigned Ffold(unsigned h) {
    return (h & 15u) ^ ((h & 16u) ? 6u : 0u);
}
__device__ __forceinline__ unsigned swzR(unsigned l) {
    return l ^ Ffold((l >> 4) & 31u);
}

// One complex 4-term linear combination, tree form (depth 2 FMA + 2 ADD).
__device__ __forceinline__ u64 lin4tree(ulonglong2 e0, ulonglong2 e1,
                                        ulonglong2 e2, ulonglong2 e3,
                                        u64 a, u64 bq, u64 c, u64 d) {
    u64 A, B, C, D, AB, CD;
    MUL2(A, e0.x, a);  FMA2(A, e0.y, swap64(a),  A);
    MUL2(B, e1.x, bq); FMA2(B, e1.y, swap64(bq), B);
    MUL2(C, e2.x, c);  FMA2(C, e2.y, swap64(c),  C);
    MUL2(D, e3.x, d);  FMA2(D, e3.y, swap64(d),  D);
    ADD2(AB, A, B);
    ADD2(CD, C, D);
    ADD2(AB, AB, CD);
    return AB;
}

// Both gate bits in lane bits LP (high), LQ (low). V[r][x] = U[r][r^x],
// rows padded to 5 ulonglong2 (80B) -> conflict-free LDS.128.
template <int LP, int LQ, int L>
__device__ __forceinline__ void bothlane(u64& v0, u64& v1, unsigned lane,
                                         const ulonglong2* __restrict__ Vt) {
    unsigned r = (((lane >> LP) & 1u) << 1) | ((lane >> LQ) & 1u);
    const ulonglong2* row = Vt + L * 20 + (int)r * 5;
    ulonglong2 e0 = row[0], e1 = row[1], e2 = row[2], e3 = row[3];
    u64 b0 = shx64(v0, 1 << LQ), b1 = shx64(v1, 1 << LQ);
    u64 c0 = shx64(v0, 1 << LP), c1 = shx64(v1, 1 << LP);
    u64 d0 = shx64(v0, (1 << LP) | (1 << LQ)), d1 = shx64(v1, (1 << LP) | (1 << LQ));
    u64 t = lin4tree(e0, e1, e2, e3, v0, b0, c0, d0);
    u64 s = lin4tree(e0, e1, e2, e3, v1, b1, c1, d1);
    v0 = t; v1 = s;
}

// High gate bit in lane bit LH, low gate bit = element bit (v0 <-> v1).
template <int LH, int L>
__device__ __forceinline__ void elemlane(u64& v0, u64& v1, unsigned lane,
                                         const ulonglong2* __restrict__ Vt) {
    unsigned bh = (lane >> LH) & 1u;
    const ulonglong2* r0p = Vt + L * 20 + (int)(bh << 1) * 5;
    const ulonglong2* r1p = r0p + 5;
    ulonglong2 a0 = r0p[0], a1 = r0p[1], a2 = r0p[2], a3 = r0p[3];
    ulonglong2 g0 = r1p[0], g1 = r1p[1], g2 = r1p[2], g3 = r1p[3];
    u64 w0 = shx64(v0, 1 << LH), w1 = shx64(v1, 1 << LH);
    u64 t = lin4tree(a0, a1, a2, a3, v0, v1, w0, w1);
    u64 s = lin4tree(g0, g1, g2, g3, v1, v0, w1, w0);
    v0 = t; v1 = s;
}

__device__ __forceinline__ unsigned sm32(const void* p) {
    return (unsigned)__cvta_generic_to_shared(p);
}
__device__ __forceinline__ unsigned mapa32(unsigned addr, unsigned rank) {
    unsigned ra;
    asm("mapa.shared::cluster.u32 %0, %1, %2;" : "=r"(ra) : "r"(addr), "r"(rank));
    return ra;
}
__device__ __forceinline__ u64 dsld64r(unsigned ra) {
    u64 v;
    asm volatile("ld.shared::cluster.b64 %0, [%1];" : "=l"(v) : "r"(ra));
    return v;
}
__device__ __forceinline__ void dsst64r(unsigned ra, u64 v) {
    asm volatile("st.shared::cluster.b64 [%0], %1;" :: "r"(ra), "l"(v) : "memory");
}
#define CLUSTER_SYNC() do { \
    asm volatile("barrier.cluster.arrive.aligned;" ::: "memory"); \
    asm volatile("barrier.cluster.wait.aligned;"   ::: "memory"); \
} while (0)

__global__ void __launch_bounds__(NT, 1)
qcnn_kernel(const float* __restrict__ pr, const float* __restrict__ pi,
            const float* __restrict__ Hr, const float* __restrict__ Hi,
            float* __restrict__ out)
{
    __shared__ u64 bufR[512];          // remap scratch (CTA-private)
    __shared__ u64 bufS[512];          // cluster exchange buffer
    __shared__ ulonglong2 Vt[80];      // V[L][r][x] = U[r][r^x], rows padded to 5
    __shared__ float2 red2[8];
    __shared__ u64 spartArr[CLUSTER];  // rank 0 only: pushed (n,s) partials

    const unsigned t    = threadIdx.x;
    const unsigned lane = t & 31u;
    const unsigned wq   = t >> 5;
    const unsigned b    = blockIdx.x >> 4;
    unsigned rank;
    asm("mov.u32 %0, %%cluster_ctarank;" : "=r"(rank));

    // ---- every thread loads its own 2 amps (map alpha: l = w | e<<3 | lane<<4,
    //      chunk bits = rank at positions 9..12) ----
    const float* prb = pr + (b << 13);
    const float* pib = pi + (b << 13);
    unsigned gi0 = (rank << 9) | wq | (lane << 4);
    u64 v0 = pack2(prb[gi0], pib[gi0]);
    u64 v1 = pack2(prb[gi0 | 8u], pib[gi0 | 8u]);
    float ns = sq64(v0) + sq64(v1);

    // ---- warps 0..3: expm(H - H^dag), one layer per warp (halves duplicate);
    //      tree-structured accumulation; writes XOR-permuted V table ----
    if (t < 128u) {
        const int L = (int)wq;
        const int e = (int)(lane & 15u);
        const int i = e >> 2, j = e & 3;
        const unsigned seg = lane & 16u;
        const float* HrL = Hr + L * 16;
        const float* HiL = Hi + L * 16;
        float ar = HrL[e] - HrL[j * 4 + i];
        float ai = HiL[e] + HiL[j * 4 + i];
        float f2 = fmaf(ar, ar, ai * ai);
#pragma unroll
        for (int o = 8; o; o >>= 1) f2 += __shfl_xor_sync(0xffffffffu, f2, o);
        float fro = sqrtf(f2);
        int s = 0; float x = fro;
        while (x > 0.25f && s < 14) { x *= 0.5f; ++s; }
        float sc = ldexpf(1.f, -s);
        float Ar = ar * sc, Ai = ai * sc;
        float Tr = Ar, Ti = Ai;
        float Er = Ar + ((i == j) ? 1.f : 0.f), Ei = Ai;
#pragma unroll 1
        for (int k = 2; k <= 9; ++k) {
            float pr0 = 0.f, pi0 = 0.f, pr1 = 0.f, pi1 = 0.f;
#pragma unroll
            for (int m = 0; m < 2; ++m) {
                unsigned sT = seg | (unsigned)(i * 4 + m);
                unsigned sA = seg | (unsigned)(m * 4 + j);
                float tr = __shfl_sync(0xffffffffu, Tr, sT);
                float ti = __shfl_sync(0xffffffffu, Ti, sT);
                float br = __shfl_sync(0xffffffffu, Ar, sA);
                float bi = __shfl_sync(0xffffffffu, Ai, sA);
                pr0 = fmaf(tr, br, fmaf(-ti, bi, pr0));
                pi0 = fmaf(tr, bi, fmaf( ti, br, pi0));
            }
#pragma unroll
            for (int m = 2; m < 4; ++m) {
                unsigned sT = seg | (unsigned)(i * 4 + m);
                unsigned sA = seg | (unsigned)(m * 4 + j);
                float tr = __shfl_sync(0xffffffffu, Tr, sT);
                float ti = __shfl_sync(0xffffffffu, Ti, sT);
                float br = __shfl_sync(0xffffffffu, Ar, sA);
                float bi = __shfl_sync(0xffffffffu, Ai, sA);
                pr1 = fmaf(tr, br, fmaf(-ti, bi, pr1));
                pi1 = fmaf(tr, bi, fmaf( ti, br, pi1));
            }
            float inv = 1.f / (float)k;
            Tr = (pr0 + pr1) * inv; Ti = (pi0 + pi1) * inv;
            Er += Tr; Ei += Ti;
        }
#pragma unroll 1
        for (int q = 0; q < s; ++q) {
            float pr0 = 0.f, pi0 = 0.f, pr1 = 0.f, pi1 = 0.f;
#pragma unroll
            for (int m = 0; m < 2; ++m) {
                unsigned sR = seg | (unsigned)(i * 4 + m);
                unsigned sC = seg | (unsigned)(m * 4 + j);
                float rr = __shfl_sync(0xffffffffu, Er, sR);
                float ri = __shfl_sync(0xffffffffu, Ei, sR);
                float cr = __shfl_sync(0xffffffffu, Er, sC);
                float ci = __shfl_sync(0xffffffffu, Ei, sC);
                pr0 = fmaf(rr, cr, fmaf(-ri, ci, pr0));
                pi0 = fmaf(rr, ci, fmaf( ri, cr, pi0));
            }
#pragma unroll
            for (int m = 2; m < 4; ++m) {
                unsigned sR = seg | (unsigned)(i * 4 + m);
                unsigned sC = seg | (unsigned)(m * 4 + j);
                float rr = __shfl_sync(0xffffffffu, Er, sR);
                float ri = __shfl_sync(0xffffffffu, Ei, sR);
                float cr = __shfl_sync(0xffffffffu, Er, sC);
                float ci = __shfl_sync(0xffffffffu, Ei, sC);
                pr1 = fmaf(rr, cr, fmaf(-ri, ci, pr1));
                pi1 = fmaf(rr, ci, fmaf( ri, cr, pi1));
            }
            Er = pr0 + pr1; Ei = pi0 + pi1;
        }
        if (lane < 16u)
            Vt[L * 20 + i * 5 + (i ^ j)] = make_ulonglong2(pack2(Er, Er), pack2(-Ei, Ei));
    }
    __syncthreads();

    // ---- Pass alpha (map: b3=e, b4..8=lane0..4, b0..2=w) ----
    bothlane<4,3,0>(v0, v1, lane, Vt);     // L0 (8,7)
    bothlane<2,1,0>(v0, v1, lane, Vt);     // L0 (6,5)
    elemlane<0,0>  (v0, v1, lane, Vt);     // L0 (4,3)
    bothlane<3,2,0>(v0, v1, lane, Vt);     // L0 (7,6)
    bothlane<1,0,0>(v0, v1, lane, Vt);     // L0 (5,4)
    bothlane<3,1,1>(v0, v1, lane, Vt);     // L1 (7,5)

    // ---- Remap alpha -> beta (b0..3=lane0..3, b4=e, b5=lane4, b6..8=w) ----
    {
        unsigned la0 = wq | (lane << 4);
        bufR[swzR(la0)]      = v0;
        bufR[swzR(la0 | 8u)] = v1;
        __syncthreads();
        unsigned lb0 = (lane & 15u) | (((lane >> 4) & 1u) << 5) | (wq << 6);
        v0 = bufR[swzR(lb0)];
        v1 = bufR[swzR(lb0 | 16u)];
    }

    // ---- Pass beta ----
    bothlane<2,1,0>(v0, v1, lane, Vt);     // L0 (2,1)
    bothlane<3,2,0>(v0, v1, lane, Vt);     // L0 (3,2)
    bothlane<1,0,0>(v0, v1, lane, Vt);     // L0 (1,0)
    bothlane<3,1,1>(v0, v1, lane, Vt);     // L1 (3,1)
    bothlane<4,3,1>(v0, v1, lane, Vt);     // L1 (5,3)
    bothlane<1,0,1>(v0, v1, lane, Vt);     // L1 (1,0)

    // ---- Cluster exchange: store (identity on local-A index), sync, DSMEM read
    {
        unsigned lb0 = (lane & 15u) | (((lane >> 4) & 1u) << 5) | (wq << 6);
        bufS[lb0]       = v0;
        bufS[lb0 | 16u] = v1;
        CLUSTER_SYNC();
        const unsigned base = sm32(bufS);
        unsigned owner = (lane >> 1) & 15u;
        unsigned lac = (wq & 3u) | ((rank & 7u) << 2) | (((wq >> 2) & 1u) << 5)
                     | (((rank >> 3) & 1u) << 6) | ((lane & 1u) << 8);
        unsigned ra = mapa32(base + lac * 8u, owner);   // one mapa, two loads
        v0 = dsld64r(ra);            // e=0 (position 7 bit = 0)
        v1 = dsld64r(ra + 1024u);    // e=1 (+128 slots * 8B)
    }

    // ---- Pass gamma (local-B; same slot map as alpha) ----
    bothlane<4,3,0>(v0, v1, lane, Vt);     // L0 (12,11)
    bothlane<2,1,0>(v0, v1, lane, Vt);     // L0 (10,9)
    bothlane<3,2,0>(v0, v1, lane, Vt);     // L0 (11,10)
    bothlane<1,0,0>(v0, v1, lane, Vt);     // L0 (9,8)
    bothlane<3,1,1>(v0, v1, lane, Vt);     // L1 (11,9)
    elemlane<1,1>  (v0, v1, lane, Vt);     // L1 (9,7): high=pos9(lane1), low=pos7(elem)

    // ---- Remap gamma -> delta (same slot permutation as alpha -> beta) ----
    {
        unsigned la0 = wq | (lane << 4);
        bufR[swzR(la0)]      = v0;
        bufR[swzR(la0 | 8u)] = v1;
        __syncthreads();
        unsigned lb0 = (lane & 15u) | (((lane >> 4) & 1u) << 5) | (wq << 6);
        v0 = bufR[swzR(lb0)];
        v1 = bufR[swzR(lb0 | 16u)];
    }

    // ---- Pass delta ----
    bothlane<4,2,2>(v0, v1, lane, Vt);     // L2 (9,5)
    bothlane<1,0,2>(v0, v1, lane, Vt);     // L2 (1,0)
    bothlane<2,1,2>(v0, v1, lane, Vt);     // L2 (5,1)
    bothlane<0,4,2>(v0, v1, lane, Vt);     // L2 (0,9): high=pos0(lane0), low=pos9(lane4)
    bothlane<2,0,3>(v0, v1, lane, Vt);     // L3 (5,0)

    // ---- Readout: P(position 0 == 0); position 0 = delta lane bit 0 ----
    float ls = (lane & 1u) ? 0.f : (sq64(v0) + sq64(v1));
#pragma unroll
    for (int o = 16; o; o >>= 1) {
        ns += __shfl_xor_sync(0xffffffffu, ns, o);
        ls += __shfl_xor_sync(0xffffffffu, ls, o);
    }
    if (lane == 0u) red2[wq] = make_float2(ns, ls);
    __syncthreads();

    // ---- Push CTA partial (n,s) to rank 0's smem; release via cluster arrive
    if (t == 0u) {
        float n = 0.f, s = 0.f;
#pragma unroll
        for (int w = 0; w < 8; ++w) { n += red2[w].x; s += red2[w].y; }
        unsigned ra = mapa32(sm32(&spartArr[rank]), 0u);
        dsst64r(ra, pack2(n, s));
    }

    // Final sync: orders the pushes before rank 0's local reads AND guarantees
    // all DSMEM reads of peers' bufS finished before any CTA exits.
    CLUSTER_SYNC();
    if (rank == 0u && t == 0u) {
        float n = 0.f, s = 0.f;
#pragma unroll
        for (unsigned r = 0; r < CLUSTER; ++r) {
            float x, y; unpack2(spartArr[r], x, y);
            n += x; s += y;
        }
        out[b] = s / n;
    }
}

extern "C" void kernel_launch(void* const* d_in, const int* in_sizes, int n_in,
                              void* d_out, int out_size) {
    (void)in_sizes; (void)n_in; (void)out_size;
    const float* pr = (const float*)d_in[0];
    const float* pi = (const float*)d_in[1];
    const float* Hr = (const float*)d_in[2];
    const float* Hi = (const float*)d_in[3];
    float* out = (float*)d_out;

    cudaFuncSetAttribute(qcnn_kernel, cudaFuncAttributeNonPortableClusterSizeAllowed, 1);

    cudaLaunchConfig_t cfg = {};
    cfg.gridDim  = dim3(NBLK, 1, 1);
    cfg.blockDim = dim3(NT, 1, 1);
    cfg.dynamicSmemBytes = 0;
    cfg.stream = 0;
    cudaLaunchAttribute attr[1];
    attr[0].id = cudaLaunchAttributeClusterDimension;
    attr[0].val.clusterDim.x = CLUSTER;
    attr[0].val.clusterDim.y = 1;
    attr[0].val.clusterDim.z = 1;
    cfg.attrs = attr;
    cfg.numAttrs = 1;

    cudaLaunchKernelEx(&cfg, qcnn_kernel, pr, pi, Hr, Hi, out);
}

// round 9
// speedup vs baseline: 1.1910x; 1.0507x over previous
#include <cuda_runtime.h>
#include <cstdint>

// ---------------------------------------------------------------------------
// QCNN 13 qubits, B=2 -> 23 two-qubit gates. Grid 32 x 256, one 16-CTA
// cluster per batch. Amplitudes live in REGISTERS (2 per thread); all 23
// gates are warp-shuffle gates (no block barrier per gate). Layout remaps:
// two smem permutes (1 syncthreads each) + one DSMEM cluster exchange.
// ---------------------------------------------------------------------------

#define NT      256
#define NBLK    32
#define CLUSTER 16

typedef unsigned long long u64;

#define FMA2(d,a,b,c) asm("fma.rn.f32x2 %0,%1,%2,%3;" : "=l"(d) : "l"(a), "l"(b), "l"(c))
#define MUL2(d,a,b)   asm("mul.rn.f32x2 %0,%1,%2;"    : "=l"(d) : "l"(a), "l"(b))

__device__ __forceinline__ u64 swap64(u64 a) {
    unsigned lo, hi;
    asm("mov.b64 {%0,%1}, %2;" : "=r"(lo), "=r"(hi) : "l"(a));
    u64 r;
    asm("mov.b64 %0, {%1,%2};" : "=l"(r) : "r"(hi), "r"(lo));
    return r;
}
__device__ __forceinline__ u64 pack2(float x, float y) {
    u64 r; asm("mov.b64 %0, {%1,%2};" : "=l"(r) : "f"(x), "f"(y)); return r;
}
__device__ __forceinline__ float sq64(u64 v) {
    float x, y; asm("mov.b64 {%0,%1}, %2;" : "=f"(x), "=f"(y) : "l"(v));
    return fmaf(x, x, y * y);
}
__device__ __forceinline__ u64 shx64(u64 v, int m) {
    return __shfl_xor_sync(0xffffffffu, v, m);
}

// Remap fold: bits 4..8 of the 9-bit local index folded into bits 0..3.
__device__ __forceinline__ unsigned Ffold(unsigned h) {
    return (h & 15u) ^ ((h & 16u) ? 6u : 0u);
}
__device__ __forceinline__ unsigned swzR(unsigned l) {
    return l ^ Ffold((l >> 4) & 31u);
}

// Both gate bits in lane bits LP (high), LQ (low). V[r][x] = U[r][r^x],
// rows padded to 5 ulonglong2 (80B) -> conflict-free LDS.128.
template <int LP, int LQ, int L>
__device__ __forceinline__ void bothlane(u64& v0, u64& v1, unsigned lane,
                                         const ulonglong2* __restrict__ Vt) {
    unsigned r = (((lane >> LP) & 1u) << 1) | ((lane >> LQ) & 1u);
    const ulonglong2* row = Vt + L * 20 + (int)r * 5;
    ulonglong2 e0 = row[0], e1 = row[1], e2 = row[2], e3 = row[3];
    u64 b0 = shx64(v0, 1 << LQ), b1 = shx64(v1, 1 << LQ);
    u64 c0 = shx64(v0, 1 << LP), c1 = shx64(v1, 1 << LP);
    u64 d0 = shx64(v0, (1 << LP) | (1 << LQ)), d1 = shx64(v1, (1 << LP) | (1 << LQ));
    u64 t, s;
    MUL2(t, e0.x, v0); FMA2(t, e0.y, swap64(v0), t);
    FMA2(t, e1.x, b0, t); FMA2(t, e1.y, swap64(b0), t);
    FMA2(t, e2.x, c0, t); FMA2(t, e2.y, swap64(c0), t);
    FMA2(t, e3.x, d0, t); FMA2(t, e3.y, swap64(d0), t);
    MUL2(s, e0.x, v1); FMA2(s, e0.y, swap64(v1), s);
    FMA2(s, e1.x, b1, s); FMA2(s, e1.y, swap64(b1), s);
    FMA2(s, e2.x, c1, s); FMA2(s, e2.y, swap64(c1), s);
    FMA2(s, e3.x, d1, s); FMA2(s, e3.y, swap64(d1), s);
    v0 = t; v1 = s;
}

// High gate bit in lane bit LH, low gate bit = element bit (v0 <-> v1).
template <int LH, int L>
__device__ __forceinline__ void elemlane(u64& v0, u64& v1, unsigned lane,
                                         const ulonglong2* __restrict__ Vt) {
    unsigned bh = (lane >> LH) & 1u;
    const ulonglong2* r0p = Vt + L * 20 + (int)(bh << 1) * 5;
    const ulonglong2* r1p = r0p + 5;
    ulonglong2 a0 = r0p[0], a1 = r0p[1], a2 = r0p[2], a3 = r0p[3];
    ulonglong2 g0 = r1p[0], g1 = r1p[1], g2 = r1p[2], g3 = r1p[3];
    u64 w0 = shx64(v0, 1 << LH), w1 = shx64(v1, 1 << LH);
    u64 t, s;
    MUL2(t, a0.x, v0); FMA2(t, a0.y, swap64(v0), t);
    FMA2(t, a1.x, v1, t); FMA2(t, a1.y, swap64(v1), t);
    FMA2(t, a2.x, w0, t); FMA2(t, a2.y, swap64(w0), t);
    FMA2(t, a3.x, w1, t); FMA2(t, a3.y, swap64(w1), t);
    MUL2(s, g0.x, v1); FMA2(s, g0.y, swap64(v1), s);
    FMA2(s, g1.x, v0, s); FMA2(s, g1.y, swap64(v0), s);
    FMA2(s, g2.x, w1, s); FMA2(s, g2.y, swap64(w1), s);
    FMA2(s, g3.x, w0, s); FMA2(s, g3.y, swap64(w0), s);
    v0 = t; v1 = s;
}

__device__ __forceinline__ unsigned sm32(const void* p) {
    return (unsigned)__cvta_generic_to_shared(p);
}

__device__ __forceinline__ u64 dsld(unsigned addr, unsigned rank) {
    unsigned ra;
    asm("mapa.shared::cluster.u32 %0, %1, %2;" : "=r"(ra) : "r"(addr), "r"(rank));
    u64 v;
    asm volatile("ld.shared::cluster.b64 %0, [%1];" : "=l"(v) : "r"(ra));
    return v;
}
__device__ __forceinline__ float2 dsldf2(unsigned addr, unsigned rank) {
    unsigned ra;
    asm("mapa.shared::cluster.u32 %0, %1, %2;" : "=r"(ra) : "r"(addr), "r"(rank));
    float x, y;
    asm volatile("ld.shared::cluster.v2.f32 {%0,%1}, [%2];" : "=f"(x), "=f"(y) : "r"(ra));
    return make_float2(x, y);
}
#define CLUSTER_SYNC() do { \
    asm volatile("barrier.cluster.arrive.aligned;" ::: "memory"); \
    asm volatile("barrier.cluster.wait.aligned;"   ::: "memory"); \
} while (0)

__global__ void __launch_bounds__(NT, 1)
qcnn_kernel(const float* __restrict__ pr, const float* __restrict__ pi,
            const float* __restrict__ Hr, const float* __restrict__ Hi,
            float* __restrict__ out)
{
    __shared__ u64 bufR[512];          // remap scratch (CTA-private)
    __shared__ u64 bufS[512];          // cluster exchange buffer
    __shared__ ulonglong2 Vt[80];      // V[L][r][x] = U[r][r^x], rows padded to 5
    __shared__ float2 red2[8];
    __shared__ float2 spart;

    const unsigned t    = threadIdx.x;
    const unsigned lane = t & 31u;
    const unsigned wq   = t >> 5;
    const unsigned b    = blockIdx.x >> 4;
    unsigned rank;
    asm("mov.u32 %0, %%cluster_ctarank;" : "=r"(rank));

    // ---- every thread loads its own 2 amps (map alpha: l = w | e<<3 | lane<<4,
    //      chunk bits = rank at positions 9..12) ----
    const float* prb = pr + (b << 13);
    const float* pib = pi + (b << 13);
    unsigned gi0 = (rank << 9) | wq | (lane << 4);
    u64 v0 = pack2(prb[gi0], pib[gi0]);
    u64 v1 = pack2(prb[gi0 | 8u], pib[gi0 | 8u]);
    float ns = sq64(v0) + sq64(v1);

    // ---- threads 0..63: shfl-based expm(H - H^dag), writes XOR-permuted V ----
    if (t < 64u) {
        const int L = (int)(t >> 4);
        const int e = (int)(t & 15u);
        const int i = e >> 2, j = e & 3;
        const unsigned seg = lane & 16u;
        const float* HrL = Hr + L * 16;
        const float* HiL = Hi + L * 16;
        float ar = HrL[e] - HrL[j * 4 + i];
        float ai = HiL[e] + HiL[j * 4 + i];
        float f2 = fmaf(ar, ar, ai * ai);
#pragma unroll
        for (int o = 8; o; o >>= 1) f2 += __shfl_xor_sync(0xffffffffu, f2, o);
        float fro = sqrtf(f2);
        int s = 0; float x = fro;
        while (x > 0.25f && s < 14) { x *= 0.5f; ++s; }
        float sc = ldexpf(1.f, -s);
        float Ar = ar * sc, Ai = ai * sc;
        float Tr = Ar, Ti = Ai;
        float Er = Ar + ((i == j) ? 1.f : 0.f), Ei = Ai;
#pragma unroll 1
        for (int k = 2; k <= 9; ++k) {
            float accr = 0.f, acci = 0.f;
#pragma unroll
            for (int m = 0; m < 4; ++m) {
                unsigned sT = seg | (unsigned)(i * 4 + m);
                unsigned sA = seg | (unsigned)(m * 4 + j);
                float tr = __shfl_sync(0xffffffffu, Tr, sT);
                float ti = __shfl_sync(0xffffffffu, Ti, sT);
                float br = __shfl_sync(0xffffffffu, Ar, sA);
                float bi = __shfl_sync(0xffffffffu, Ai, sA);
                accr = fmaf(tr, br, fmaf(-ti, bi, accr));
                acci = fmaf(tr, bi, fmaf( ti, br, acci));
            }
            float inv = 1.f / (float)k;
            Tr = accr * inv; Ti = acci * inv;
            Er += Tr; Ei += Ti;
        }
        int smax = s;
#pragma unroll
        for (int o = 16; o; o >>= 1) {
            int v = __shfl_xor_sync(0xffffffffu, smax, o);
            smax = v > smax ? v : smax;
        }
#pragma unroll 1
        for (int q = 0; q < smax; ++q) {
            float accr = 0.f, acci = 0.f;
#pragma unroll
            for (int m = 0; m < 4; ++m) {
                unsigned sR = seg | (unsigned)(i * 4 + m);
                unsigned sC = seg | (unsigned)(m * 4 + j);
                float rr = __shfl_sync(0xffffffffu, Er, sR);
                float ri = __shfl_sync(0xffffffffu, Ei, sR);
                float cr = __shfl_sync(0xffffffffu, Er, sC);
                float ci = __shfl_sync(0xffffffffu, Ei, sC);
                accr = fmaf(rr, cr, fmaf(-ri, ci, accr));
                acci = fmaf(rr, ci, fmaf( ri, cr, acci));
            }
            if (q < s) { Er = accr; Ei = acci; }
        }
        Vt[L * 20 + i * 5 + (i ^ j)] = make_ulonglong2(pack2(Er, Er), pack2(-Ei, Ei));
    }
    __syncthreads();

    // ---- Pass alpha (map: b3=e, b4..8=lane0..4, b0..2=w) ----
    bothlane<4,3,0>(v0, v1, lane, Vt);     // L0 (8,7)
    bothlane<2,1,0>(v0, v1, lane, Vt);     // L0 (6,5)
    elemlane<0,0>  (v0, v1, lane, Vt);     // L0 (4,3)
    bothlane<3,2,0>(v0, v1, lane, Vt);     // L0 (7,6)
    bothlane<1,0,0>(v0, v1, lane, Vt);     // L0 (5,4)
    bothlane<3,1,1>(v0, v1, lane, Vt);     // L1 (7,5)

    // ---- Remap alpha -> beta (b0..3=lane0..3, b4=e, b5=lane4, b6..8=w) ----
    {
        unsigned la0 = wq | (lane << 4);
        bufR[swzR(la0)]      = v0;
        bufR[swzR(la0 | 8u)] = v1;
        __syncthreads();
        unsigned lb0 = (lane & 15u) | (((lane >> 4) & 1u) << 5) | (wq << 6);
        v0 = bufR[swzR(lb0)];
        v1 = bufR[swzR(lb0 | 16u)];
    }

    // ---- Pass beta ----
    bothlane<2,1,0>(v0, v1, lane, Vt);     // L0 (2,1)
    bothlane<3,2,0>(v0, v1, lane, Vt);     // L0 (3,2)
    bothlane<1,0,0>(v0, v1, lane, Vt);     // L0 (1,0)
    bothlane<3,1,1>(v0, v1, lane, Vt);     // L1 (3,1)
    bothlane<4,3,1>(v0, v1, lane, Vt);     // L1 (5,3)
    bothlane<1,0,1>(v0, v1, lane, Vt);     // L1 (1,0)

    // ---- Cluster exchange: store (identity on local-A index), sync, DSMEM read
    {
        unsigned lb0 = (lane & 15u) | (((lane >> 4) & 1u) << 5) | (wq << 6);
        bufS[lb0]       = v0;
        bufS[lb0 | 16u] = v1;
        CLUSTER_SYNC();
        const unsigned base = sm32(bufS);
        unsigned owner = (lane >> 1) & 15u;
        unsigned lac = (wq & 3u) | ((rank & 7u) << 2) | (((wq >> 2) & 1u) << 5)
                     | (((rank >> 3) & 1u) << 6) | ((lane & 1u) << 8);
        v0 = dsld(base + lac * 8u, owner);            // e=0 (position 7 bit = 0)
        v1 = dsld(base + (lac | 128u) * 8u, owner);   // e=1
    }

    // ---- Pass gamma (local-B; same slot map as alpha) ----
    bothlane<4,3,0>(v0, v1, lane, Vt);     // L0 (12,11)
    bothlane<2,1,0>(v0, v1, lane, Vt);     // L0 (10,9)
    bothlane<3,2,0>(v0, v1, lane, Vt);     // L0 (11,10)
    bothlane<1,0,0>(v0, v1, lane, Vt);     // L0 (9,8)
    bothlane<3,1,1>(v0, v1, lane, Vt);     // L1 (11,9)
    elemlane<1,1>  (v0, v1, lane, Vt);     // L1 (9,7): high=pos9(lane1), low=pos7(elem)

    // ---- Remap gamma -> delta (same slot permutation as alpha -> beta) ----
    {
        unsigned la0 = wq | (lane << 4);
        bufR[swzR(la0)]      = v0;
        bufR[swzR(la0 | 8u)] = v1;
        __syncthreads();
        unsigned lb0 = (lane & 15u) | (((lane >> 4) & 1u) << 5) | (wq << 6);
        v0 = bufR[swzR(lb0)];
        v1 = bufR[swzR(lb0 | 16u)];
    }

    // ---- Pass delta ----
    bothlane<4,2,2>(v0, v1, lane, Vt);     // L2 (9,5)
    bothlane<1,0,2>(v0, v1, lane, Vt);     // L2 (1,0)
    bothlane<2,1,2>(v0, v1, lane, Vt);     // L2 (5,1)
    bothlane<0,4,2>(v0, v1, lane, Vt);     // L2 (0,9): high=pos0(lane0), low=pos9(lane4)
    bothlane<2,0,3>(v0, v1, lane, Vt);     // L3 (5,0)

    // ---- Readout: P(position 0 == 0); position 0 = delta lane bit 0 ----
    float ls = (lane & 1u) ? 0.f : (sq64(v0) + sq64(v1));
#pragma unroll
    for (int o = 16; o; o >>= 1) {
        ns += __shfl_xor_sync(0xffffffffu, ns, o);
        ls += __shfl_xor_sync(0xffffffffu, ls, o);
    }
    if (lane == 0u) red2[wq] = make_float2(ns, ls);
    __syncthreads();
    if (t == 0u) {
        float n = 0.f, s = 0.f;
#pragma unroll
        for (int w = 0; w < 8; ++w) { n += red2[w].x; s += red2[w].y; }
        spart = make_float2(n, s);
    }

    // ---- Final reduction over DSMEM (deterministic fixed order) ----
    CLUSTER_SYNC();
    if (rank == 0u && t == 0u) {
        const unsigned pa = sm32(&spart);
        float n = 0.f, s = 0.f;
#pragma unroll
        for (unsigned r = 0; r < CLUSTER; ++r) {
            float2 p = dsldf2(pa, r);
            n += p.x; s += p.y;
        }
        out[b] = s / n;
    }
    CLUSTER_SYNC();   // keep peers' smem alive until rank 0 finished reading
}

extern "C" void kernel_launch(void* const* d_in, const int* in_sizes, int n_in,
                              void* d_out, int out_size) {
    (void)in_sizes; (void)n_in; (void)out_size;
    const float* pr = (const float*)d_in[0];
    const float* pi = (const float*)d_in[1];
    const float* Hr = (const float*)d_in[2];
    const float* Hi = (const float*)d_in[3];
    float* out = (float*)d_out;

    cudaFuncSetAttribute(qcnn_kernel, cudaFuncAttributeNonPortableClusterSizeAllowed, 1);

    cudaLaunchConfig_t cfg = {};
    cfg.gridDim  = dim3(NBLK, 1, 1);
    cfg.blockDim = dim3(NT, 1, 1);
    cfg.dynamicSmemBytes = 0;
    cfg.stream = 0;
    cudaLaunchAttribute attr[1];
    attr[0].id = cudaLaunchAttributeClusterDimension;
    attr[0].val.clusterDim.x = CLUSTER;
    attr[0].val.clusterDim.y = 1;
    attr[0].val.clusterDim.z = 1;
    cfg.attrs = attr;
    cfg.numAttrs = 1;

    cudaLaunchKernelEx(&cfg, qcnn_kernel, pr, pi, Hr, Hi, out);
}

// round 10
// speedup vs baseline: 1.2165x; 1.0213x over previous
#include <cuda_runtime.h>
#include <cstdint>

// ---------------------------------------------------------------------------
// QCNN 13 qubits, B=2 -> 23 two-qubit gates. Grid 32 x 256, one 16-CTA
// cluster per batch. Amplitudes in registers (2/thread); all 23 gates are
// warp-shuffle gates. R10: the phase exchange and the final reduction are
// PUSH-based (st.async + mbarrier complete_tx) -> only ONE cluster barrier,
// at kernel start. No CTA ever reads peer smem.
// ---------------------------------------------------------------------------

#define NT      256
#define NBLK    32
#define CLUSTER 16

typedef unsigned long long u64;

#define FMA2(d,a,b,c) asm("fma.rn.f32x2 %0,%1,%2,%3;" : "=l"(d) : "l"(a), "l"(b), "l"(c))
#define MUL2(d,a,b)   asm("mul.rn.f32x2 %0,%1,%2;"    : "=l"(d) : "l"(a), "l"(b))

__device__ __forceinline__ u64 swap64(u64 a) {
    unsigned lo, hi;
    asm("mov.b64 {%0,%1}, %2;" : "=r"(lo), "=r"(hi) : "l"(a));
    u64 r;
    asm("mov.b64 %0, {%1,%2};" : "=l"(r) : "r"(hi), "r"(lo));
    return r;
}
__device__ __forceinline__ u64 pack2(float x, float y) {
    u64 r; asm("mov.b64 %0, {%1,%2};" : "=l"(r) : "f"(x), "f"(y)); return r;
}
__device__ __forceinline__ void unpack2(u64 v, float& x, float& y) {
    asm("mov.b64 {%0,%1}, %2;" : "=f"(x), "=f"(y) : "l"(v));
}
__device__ __forceinline__ float sq64(u64 v) {
    float x, y; unpack2(v, x, y);
    return fmaf(x, x, y * y);
}
__device__ __forceinline__ u64 shx64(u64 v, int m) {
    return __shfl_xor_sync(0xffffffffu, v, m);
}

// Remap fold: bits 4..8 of the 9-bit local index folded into bits 0..3.
__device__ __forceinline__ unsigned Ffold(unsigned h) {
    return (h & 15u) ^ ((h & 16u) ? 6u : 0u);
}
__device__ __forceinline__ unsigned swzR(unsigned l) {
    return l ^ Ffold((l >> 4) & 31u);
}

// Both gate bits in lane bits LP (high), LQ (low). V[r][x] = U[r][r^x],
// rows padded to 5 ulonglong2 (80B) -> conflict-free LDS.128.
template <int LP, int LQ, int L>
__device__ __forceinline__ void bothlane(u64& v0, u64& v1, unsigned lane,
                                         const ulonglong2* __restrict__ Vt) {
    unsigned r = (((lane >> LP) & 1u) << 1) | ((lane >> LQ) & 1u);
    const ulonglong2* row = Vt + L * 20 + (int)r * 5;
    ulonglong2 e0 = row[0], e1 = row[1], e2 = row[2], e3 = row[3];
    u64 b0 = shx64(v0, 1 << LQ), b1 = shx64(v1, 1 << LQ);
    u64 c0 = shx64(v0, 1 << LP), c1 = shx64(v1, 1 << LP);
    u64 d0 = shx64(v0, (1 << LP) | (1 << LQ)), d1 = shx64(v1, (1 << LP) | (1 << LQ));
    u64 t, s;
    MUL2(t, e0.x, v0); FMA2(t, e0.y, swap64(v0), t);
    FMA2(t, e1.x, b0, t); FMA2(t, e1.y, swap64(b0), t);
    FMA2(t, e2.x, c0, t); FMA2(t, e2.y, swap64(c0), t);
    FMA2(t, e3.x, d0, t); FMA2(t, e3.y, swap64(d0), t);
    MUL2(s, e0.x, v1); FMA2(s, e0.y, swap64(v1), s);
    FMA2(s, e1.x, b1, s); FMA2(s, e1.y, swap64(b1), s);
    FMA2(s, e2.x, c1, s); FMA2(s, e2.y, swap64(c1), s);
    FMA2(s, e3.x, d1, s); FMA2(s, e3.y, swap64(d1), s);
    v0 = t; v1 = s;
}

// High gate bit in lane bit LH, low gate bit = element bit (v0 <-> v1).
template <int LH, int L>
__device__ __forceinline__ void elemlane(u64& v0, u64& v1, unsigned lane,
                                         const ulonglong2* __restrict__ Vt) {
    unsigned bh = (lane >> LH) & 1u;
    const ulonglong2* r0p = Vt + L * 20 + (int)(bh << 1) * 5;
    const ulonglong2* r1p = r0p + 5;
    ulonglong2 a0 = r0p[0], a1 = r0p[1], a2 = r0p[2], a3 = r0p[3];
    ulonglong2 g0 = r1p[0], g1 = r1p[1], g2 = r1p[2], g3 = r1p[3];
    u64 w0 = shx64(v0, 1 << LH), w1 = shx64(v1, 1 << LH);
    u64 t, s;
    MUL2(t, a0.x, v0); FMA2(t, a0.y, swap64(v0), t);
    FMA2(t, a1.x, v1, t); FMA2(t, a1.y, swap64(v1), t);
    FMA2(t, a2.x, w0, t); FMA2(t, a2.y, swap64(w0), t);
    FMA2(t, a3.x, w1, t); FMA2(t, a3.y, swap64(w1), t);
    MUL2(s, g0.x, v1); FMA2(s, g0.y, swap64(v1), s);
    FMA2(s, g1.x, v0, s); FMA2(s, g1.y, swap64(v0), s);
    FMA2(s, g2.x, w1, s); FMA2(s, g2.y, swap64(w1), s);
    FMA2(s, g3.x, w0, s); FMA2(s, g3.y, swap64(w0), s);
    v0 = t; v1 = s;
}

__device__ __forceinline__ unsigned sm32(const void* p) {
    return (unsigned)__cvta_generic_to_shared(p);
}
__device__ __forceinline__ unsigned mapa32(unsigned addr, unsigned rank) {
    unsigned ra;
    asm("mapa.shared::cluster.u32 %0, %1, %2;" : "=r"(ra) : "r"(addr), "r"(rank));
    return ra;
}
__device__ __forceinline__ void mbar_init(unsigned addr, unsigned cnt) {
    asm volatile("mbarrier.init.shared.b64 [%0], %1;" :: "r"(addr), "r"(cnt) : "memory");
}
__device__ __forceinline__ void mbar_expect_tx(unsigned addr, unsigned bytes) {
    asm volatile("mbarrier.arrive.expect_tx.shared.b64 _, [%0], %1;"
                 :: "r"(addr), "r"(bytes) : "memory");
}
__device__ __forceinline__ void st_async64(unsigned ra, u64 v, unsigned rm) {
    asm volatile("st.async.shared::cluster.mbarrier::complete_tx::bytes.b64 [%0], %1, [%2];"
                 :: "r"(ra), "l"(v), "r"(rm) : "memory");
}
__device__ __forceinline__ void mbar_wait(unsigned addr, unsigned parity) {
    asm volatile(
        "{\n\t.reg .pred p;\n"
        "WAIT_%=:\n\t"
        "mbarrier.try_wait.parity.acquire.cluster.shared::cta.b64 p, [%0], %1;\n\t"
        "@!p bra WAIT_%=;\n\t}"
        :: "r"(addr), "r"(parity) : "memory");
}
#define CLUSTER_SYNC() do { \
    asm volatile("barrier.cluster.arrive.aligned;" ::: "memory"); \
    asm volatile("barrier.cluster.wait.aligned;"   ::: "memory"); \
} while (0)

__global__ void __launch_bounds__(NT, 1)
qcnn_kernel(const float* __restrict__ pr, const float* __restrict__ pi,
            const float* __restrict__ Hr, const float* __restrict__ Hi,
            float* __restrict__ out)
{
    __shared__ u64 bufR[512];          // remap scratch (CTA-private)
    __shared__ u64 bufS[512];          // exchange receive buffer (written by peers)
    __shared__ ulonglong2 Vt[80];      // V[L][r][x] = U[r][r^x], rows padded to 5
    __shared__ float2 red2[8];
    __shared__ u64 spartArr[CLUSTER];  // rank 0: pushed (n,s) partials
    __shared__ u64 mbar_ex;            // exchange mbarrier (expects 4096 B)
    __shared__ u64 mbar_red;           // reduction mbarrier (rank 0, expects 128 B)

    const unsigned t    = threadIdx.x;
    const unsigned lane = t & 31u;
    const unsigned wq   = t >> 5;
    const unsigned b    = blockIdx.x >> 4;
    unsigned rank;
    asm("mov.u32 %0, %%cluster_ctarank;" : "=r"(rank));

    // ---- mbarrier init + ONE cluster barrier (at launch, skew minimal) ----
    if (t == 0u) {
        mbar_init(sm32(&mbar_ex), 1u);
        mbar_init(sm32(&mbar_red), 1u);
        asm volatile("fence.mbarrier_init.release.cluster;" ::: "memory");
    }
    __syncthreads();
    CLUSTER_SYNC();
    if (t == 0u) {
        mbar_expect_tx(sm32(&mbar_ex), 512u * 8u);
        if (rank == 0u) mbar_expect_tx(sm32(&mbar_red), CLUSTER * 8u);
    }

    // ---- every thread loads its own 2 amps (map alpha: l = w | e<<3 | lane<<4,
    //      chunk bits = rank at positions 9..12) ----
    const float* prb = pr + (b << 13);
    const float* pib = pi + (b << 13);
    unsigned gi0 = (rank << 9) | wq | (lane << 4);
    u64 v0 = pack2(prb[gi0], pib[gi0]);
    u64 v1 = pack2(prb[gi0 | 8u], pib[gi0 | 8u]);
    float ns = sq64(v0) + sq64(v1);

    // ---- threads 0..63: shfl-based expm(H - H^dag), writes XOR-permuted V ----
    if (t < 64u) {
        const int L = (int)(t >> 4);
        const int e = (int)(t & 15u);
        const int i = e >> 2, j = e & 3;
        const unsigned seg = lane & 16u;
        const float* HrL = Hr + L * 16;
        const float* HiL = Hi + L * 16;
        float ar = HrL[e] - HrL[j * 4 + i];
        float ai = HiL[e] + HiL[j * 4 + i];
        float f2 = fmaf(ar, ar, ai * ai);
#pragma unroll
        for (int o = 8; o; o >>= 1) f2 += __shfl_xor_sync(0xffffffffu, f2, o);
        float fro = sqrtf(f2);
        int s = 0; float x = fro;
        while (x > 0.25f && s < 14) { x *= 0.5f; ++s; }
        float sc = ldexpf(1.f, -s);
        float Ar = ar * sc, Ai = ai * sc;
        float Tr = Ar, Ti = Ai;
        float Er = Ar + ((i == j) ? 1.f : 0.f), Ei = Ai;
#pragma unroll 1
        for (int k = 2; k <= 9; ++k) {
            float accr = 0.f, acci = 0.f;
#pragma unroll
            for (int m = 0; m < 4; ++m) {
                unsigned sT = seg | (unsigned)(i * 4 + m);
                unsigned sA = seg | (unsigned)(m * 4 + j);
                float tr = __shfl_sync(0xffffffffu, Tr, sT);
                float ti = __shfl_sync(0xffffffffu, Ti, sT);
                float br = __shfl_sync(0xffffffffu, Ar, sA);
                float bi = __shfl_sync(0xffffffffu, Ai, sA);
                accr = fmaf(tr, br, fmaf(-ti, bi, accr));
                acci = fmaf(tr, bi, fmaf( ti, br, acci));
            }
            float inv = 1.f / (float)k;
            Tr = accr * inv; Ti = acci * inv;
            Er += Tr; Ei += Ti;
        }
        int smax = s;
#pragma unroll
        for (int o = 16; o; o >>= 1) {
            int v = __shfl_xor_sync(0xffffffffu, smax, o);
            smax = v > smax ? v : smax;
        }
#pragma unroll 1
        for (int q = 0; q < smax; ++q) {
            float accr = 0.f, acci = 0.f;
#pragma unroll
            for (int m = 0; m < 4; ++m) {
                unsigned sR = seg | (unsigned)(i * 4 + m);
                unsigned sC = seg | (unsigned)(m * 4 + j);
                float rr = __shfl_sync(0xffffffffu, Er, sR);
                float ri = __shfl_sync(0xffffffffu, Ei, sR);
                float cr = __shfl_sync(0xffffffffu, Er, sC);
                float ci = __shfl_sync(0xffffffffu, Ei, sC);
                accr = fmaf(rr, cr, fmaf(-ri, ci, accr));
                acci = fmaf(rr, ci, fmaf( ri, cr, acci));
            }
            if (q < s) { Er = accr; Ei = acci; }
        }
        Vt[L * 20 + i * 5 + (i ^ j)] = make_ulonglong2(pack2(Er, Er), pack2(-Ei, Ei));
    }
    __syncthreads();

    // ---- Pass alpha (map: b3=e, b4..8=lane0..4, b0..2=w) ----
    bothlane<4,3,0>(v0, v1, lane, Vt);     // L0 (8,7)
    bothlane<2,1,0>(v0, v1, lane, Vt);     // L0 (6,5)
    elemlane<0,0>  (v0, v1, lane, Vt);     // L0 (4,3)
    bothlane<3,2,0>(v0, v1, lane, Vt);     // L0 (7,6)
    bothlane<1,0,0>(v0, v1, lane, Vt);     // L0 (5,4)
    bothlane<3,1,1>(v0, v1, lane, Vt);     // L1 (7,5)

    // ---- Remap alpha -> beta (b0..3=lane0..3, b4=e, b5=lane4, b6..8=w) ----
    {
        unsigned la0 = wq | (lane << 4);
        bufR[swzR(la0)]      = v0;
        bufR[swzR(la0 | 8u)] = v1;
        __syncthreads();
        unsigned lb0 = (lane & 15u) | (((lane >> 4) & 1u) << 5) | (wq << 6);
        v0 = bufR[swzR(lb0)];
        v1 = bufR[swzR(lb0 | 16u)];
    }

    // ---- Pass beta ----
    bothlane<2,1,0>(v0, v1, lane, Vt);     // L0 (2,1)
    bothlane<3,2,0>(v0, v1, lane, Vt);     // L0 (3,2)
    bothlane<1,0,0>(v0, v1, lane, Vt);     // L0 (1,0)
    bothlane<3,1,1>(v0, v1, lane, Vt);     // L1 (3,1)
    bothlane<4,3,1>(v0, v1, lane, Vt);     // L1 (5,3)
    bothlane<1,0,1>(v0, v1, lane, Vt);     // L1 (1,0)

    // ---- PUSH exchange: for each amp (beta-local index l, identity on
    //      positions), dest CTA = l{2,3,4,6}; dest slot = lane' | wq'<<5 | e'<<8
    //      with wq' = l{0,1,5}, lane' = l8 | rank<<1, e' = l7
    //      (exact inverse of the round-5 verified pull formula). ----
    {
        unsigned lb0 = (lane & 15u) | (((lane >> 4) & 1u) << 5) | (wq << 6);
        const unsigned bufS_a = sm32(bufS);
        const unsigned mbar_a = sm32(&mbar_ex);
#pragma unroll
        for (int kk = 0; kk < 2; ++kk) {
            unsigned l   = kk ? (lb0 | 16u) : lb0;
            u64 val      = kk ? v1 : v0;
            unsigned dst = ((l >> 2) & 7u) | (((l >> 6) & 1u) << 3);
            unsigned wqp = (l & 3u) | (((l >> 5) & 1u) << 2);
            unsigned m   = ((l >> 8) & 1u) | (rank << 1) | (wqp << 5) | (((l >> 7) & 1u) << 8);
            unsigned ra  = mapa32(bufS_a + m * 8u, dst);
            unsigned rm  = mapa32(mbar_a, dst);
            st_async64(ra, val, rm);
        }
        // wait for our full 512-amp gamma chunk (4096 bytes) to arrive
        mbar_wait(sm32(&mbar_ex), 0u);
        v0 = bufS[lane | (wq << 5)];           // e=0
        v1 = bufS[lane | (wq << 5) | 256u];    // e=1
    }

    // ---- Pass gamma (local-B; same slot map as alpha) ----
    bothlane<4,3,0>(v0, v1, lane, Vt);     // L0 (12,11)
    bothlane<2,1,0>(v0, v1, lane, Vt);     // L0 (10,9)
    bothlane<3,2,0>(v0, v1, lane, Vt);     // L0 (11,10)
    bothlane<1,0,0>(v0, v1, lane, Vt);     // L0 (9,8)
    bothlane<3,1,1>(v0, v1, lane, Vt);     // L1 (11,9)
    elemlane<1,1>  (v0, v1, lane, Vt);     // L1 (9,7): high=pos9(lane1), low=pos7(elem)

    // ---- Remap gamma -> delta (same slot permutation as alpha -> beta) ----
    {
        unsigned la0 = wq | (lane << 4);
        __syncthreads();                   // bufR reuse: prior loads done
        bufR[swzR(la0)]      = v0;
        bufR[swzR(la0 | 8u)] = v1;
        __syncthreads();
        unsigned lb0 = (lane & 15u) | (((lane >> 4) & 1u) << 5) | (wq << 6);
        v0 = bufR[swzR(lb0)];
        v1 = bufR[swzR(lb0 | 16u)];
    }

    // ---- Pass delta ----
    bothlane<4,2,2>(v0, v1, lane, Vt);     // L2 (9,5)
    bothlane<1,0,2>(v0, v1, lane, Vt);     // L2 (1,0)
    bothlane<2,1,2>(v0, v1, lane, Vt);     // L2 (5,1)
    bothlane<0,4,2>(v0, v1, lane, Vt);     // L2 (0,9): high=pos0(lane0), low=pos9(lane4)
    bothlane<2,0,3>(v0, v1, lane, Vt);     // L3 (5,0)

    // ---- Readout: P(position 0 == 0); position 0 = delta lane bit 0 ----
    float ls = (lane & 1u) ? 0.f : (sq64(v0) + sq64(v1));
#pragma unroll
    for (int o = 16; o; o >>= 1) {
        ns += __shfl_xor_sync(0xffffffffu, ns, o);
        ls += __shfl_xor_sync(0xffffffffu, ls, o);
    }
    if (lane == 0u) red2[wq] = make_float2(ns, ls);
    __syncthreads();

    // ---- Push CTA partial (n,s) to rank 0 via st.async; rank 0 waits on
    //      its reduction mbarrier (128 bytes) then writes out. No final
    //      cluster barrier: no CTA reads peer smem anywhere. ----
    if (t == 0u) {
        float n = 0.f, s = 0.f;
#pragma unroll
        for (int w = 0; w < 8; ++w) { n += red2[w].x; s += red2[w].y; }
        unsigned ra = mapa32(sm32(&spartArr[rank]), 0u);
        unsigned rm = mapa32(sm32(&mbar_red), 0u);
        st_async64(ra, pack2(n, s), rm);
        if (rank == 0u) {
            mbar_wait(sm32(&mbar_red), 0u);
            float nn = 0.f, ss = 0.f;
#pragma unroll
            for (unsigned r = 0; r < CLUSTER; ++r) {
                float x, y; unpack2(spartArr[r], x, y);
                nn += x; ss += y;
            }
            out[b] = ss / nn;
        }
    }
}

extern "C" void kernel_launch(void* const* d_in, const int* in_sizes, int n_in,
                              void* d_out, int out_size) {
    (void)in_sizes; (void)n_in; (void)out_size;
    const float* pr = (const float*)d_in[0];
    const float* pi = (const float*)d_in[1];
    const float* Hr = (const float*)d_in[2];
    const float* Hi = (const float*)d_in[3];
    float* out = (float*)d_out;

    cudaFuncSetAttribute(qcnn_kernel, cudaFuncAttributeNonPortableClusterSizeAllowed, 1);

    cudaLaunchConfig_t cfg = {};
    cfg.gridDim  = dim3(NBLK, 1, 1);
    cfg.blockDim = dim3(NT, 1, 1);
    cfg.dynamicSmemBytes = 0;
    cfg.stream = 0;
    cudaLaunchAttribute attr[1];
    attr[0].id = cudaLaunchAttributeClusterDimension;
    attr[0].val.clusterDim.x = CLUSTER;
    attr[0].val.clusterDim.y = 1;
    attr[0].val.clusterDim.z = 1;
    cfg.attrs = attr;
    cfg.numAttrs = 1;

    cudaLaunchKernelEx(&cfg, qcnn_kernel, pr, pi, Hr, Hi, out);
}